// round 15
// baseline (speedup 1.0000x reference)
#include <cuda_runtime.h>
#include <cuda_fp16.h>
#include <cstdint>
#include <math.h>

#define CIN   64
#define COUT  128
#define HH    224
#define WW    224
#define OH    222
#define OW    222

#define TPX    16
#define TROWS  8
#define PXST   18
#define SLAB_STRIDE 3072

#define NTX 14
#define NTY 28
#define PB  896            // prep blocks per batch  (4 x 224)
#define CB  392            // conv blocks per batch  (14 x 28)
#define BPB (PB + CB)      // 1288
#define NCONV 6272         // 16 * CB

// ---------------- global scratch ----------------
__device__ __half g_xh[(size_t)16 * HH * WW * CIN];
__device__ uint4 g_Wfrag[9 * 4 * 8 * 32];
__device__ int g_flag[16 * HH];
__device__ int g_cons[16 * HH];
__device__ int g_wflag;
__device__ int g_wcons;

// ---------------- helpers ----------------
__device__ __forceinline__ uint32_t smem_u32(const void* p) {
    uint32_t a;
    asm("{ .reg .u64 t; cvta.to.shared.u64 t, %1; cvt.u32.u64 %0, t; }" : "=r"(a) : "l"(p));
    return a;
}
__device__ __forceinline__ void ldsm4(uint32_t& r0, uint32_t& r1, uint32_t& r2, uint32_t& r3, uint32_t addr) {
    asm volatile("ldmatrix.sync.aligned.m8n8.x4.shared.b16 {%0, %1, %2, %3}, [%4];"
        : "=r"(r0), "=r"(r1), "=r"(r2), "=r"(r3) : "r"(addr));
}
__device__ __forceinline__ void mma16816(float* d, const uint4& a, uint32_t b0, uint32_t b1) {
    asm volatile("mma.sync.aligned.m16n8k16.row.col.f32.f16.f16.f32 "
        "{%0, %1, %2, %3}, {%4, %5, %6, %7}, {%8, %9}, {%0, %1, %2, %3};"
        : "+f"(d[0]), "+f"(d[1]), "+f"(d[2]), "+f"(d[3])
        : "r"(a.x), "r"(a.y), "r"(a.z), "r"(a.w), "r"(b0), "r"(b1));
}
__device__ __forceinline__ void cp16(uint32_t dst, const void* src, int sz) {
    asm volatile("cp.async.cg.shared.global [%0], [%1], 16, %2;"
        :: "r"(dst), "l"(src), "r"(sz) : "memory");
}
__device__ __forceinline__ void sts128(uint32_t addr, uint32_t r0, uint32_t r1, uint32_t r2, uint32_t r3) {
    asm volatile("st.shared.v4.b32 [%0], {%1, %2, %3, %4};" :: "r"(addr), "r"(r0), "r"(r1), "r"(r2), "r"(r3) : "memory");
}
__device__ __forceinline__ uint32_t swz(uint32_t off) { return off ^ ((off >> 3) & 0x70); }

__device__ __forceinline__ bool spin_ge(volatile int* p, int val, int iters) {
    for (int i = 0; i < iters; i++) {
        if (*p >= val) return true;
        __nanosleep(128);
    }
    return (*p >= val);
}

#define OFF_MIN (16 * SLAB_STRIDE)                // 49152
#define SMEM_BYTES (OFF_MIN + 1024 + 1024)        // 51200
#define TSTR 72

__global__ __launch_bounds__(256, 2)
void fused_kernel(const float* __restrict__ x,
                  const float* __restrict__ w,
                  const float* __restrict__ bias,
                  float* __restrict__ out) {
    extern __shared__ char smem_raw[];
    const int bid = blockIdx.x;
    const int b   = bid / BPB;
    const int r   = bid - b * BPB;
    const int tid  = threadIdx.x;
    const int wid  = tid >> 5;
    const int lane = tid & 31;

    if (r < PB) {
        // ===================== PREP ROLE =====================
        __half* sT = (__half*)smem_raw;           // [64 px][TSTR]
        const int y       = r >> 2;
        const int quarter = r & 3;
        const int px0     = quarter * 64;
        const bool isWblk = (b == 0) && (quarter == 0) && (y < 9);

        if (isWblk) {
#pragma unroll
            for (int rep = 0; rep < 4; rep++) {
                int i = (y * 4 + rep) * 256 + tid;
                int ln   = i & 31;
                int mblk = (i >> 5) & 7;
                int q    = i >> 8;
                int ks   = q & 3;
                int tap  = q >> 2;
                int kh = tap / 3, kw = tap - kh * 3;
                int rr = ln >> 2;
                int k0 = ks * 16 + (ln & 3) * 2;
                uint32_t words[4];
#pragma unroll
                for (int wi = 0; wi < 4; wi++) {
                    int co = mblk * 16 + rr + (wi & 1) * 8;
                    int kk = k0 + (wi >> 1) * 8;
                    uint32_t packed = 0;
#pragma unroll
                    for (int j = 0; j < 2; j++) {
                        float v = w[((co * CIN + (kk + j)) * 3 + kh) * 3 + kw];
                        packed |= (uint32_t)__half_as_ushort(__float2half(v)) << (16 * j);
                    }
                    words[wi] = packed;
                }
                g_Wfrag[i] = make_uint4(words[0], words[1], words[2], words[3]);
            }
        }

        const int px = ((wid & 1) * 32) + lane;
        const int ip = px0 + px;
        const bool okx = ip < WW;
        const int cib = wid >> 1;
#pragma unroll
        for (int k = 0; k < 16; k++) {
            int ci = cib + k * 4;
            float v = okx ? __ldg(&x[(((size_t)b * CIN + ci) * HH + y) * WW + ip]) : 0.0f;
            sT[px * TSTR + ci] = __float2half(v);
        }
        __syncthreads();

        for (int c = tid; c < 512; c += 256) {
            int pxw = c >> 3, cig = c & 7;
            int ipw = px0 + pxw;
            if (ipw < WW) {
                uint4 val = *(const uint4*)&sT[pxw * TSTR + cig * 8];
                *(uint4*)((char*)g_xh + (((size_t)(b * HH + y) * WW + ipw) << 7) + (cig << 4)) = val;
            }
        }
        __threadfence();
        __syncthreads();
        if (tid == 0) {
            atomicAdd(&g_flag[b * HH + y], 1);
            if (isWblk) atomicAdd(&g_wflag, 1);
        }
        return;
    }

    // ===================== CONV ROLE =====================
    uint32_t sb = (smem_u32(smem_raw) + 1023u) & ~1023u;
    const int t   = r - PB;
    const int bx  = t % NTX;
    const int ty  = t / NTX;
    const int oy0 = ty * TROWS;
    const int x0  = bx * TPX;

    const int warpM = wid & 1;
    const int pair  = wid >> 1;
    const uint32_t pairbase = sb + (uint32_t)(pair * 4 * SLAB_STRIDE);

    // ---- per-pair staging with producer flags ----
#pragma unroll
    for (int s = 0; s < 2; s++) {
        const int j = warpM + 2 * s;
        const int y = oy0 + 2 * pair + j;
        int ready = 1;
        if (y < HH) {
            if (lane == 0) ready = spin_ge(&g_flag[b * HH + y], 4, 20000) ? 1 : 0;
            ready = __shfl_sync(0xffffffffu, ready, 0);
        }
        if (ready) {
            if (y < HH) __threadfence();   // acquire side
#pragma unroll 1
            for (int c = lane; c < PXST * 8; c += 32) {
                int px  = c >> 3;
                int cig = c & 7;
                int ix  = x0 + px;
                bool ok = (y < HH) && (ix < WW);
                const char* src = (const char*)g_xh +
                    (ok ? ((((size_t)(b * HH + y) * WW + ix) << 7) + ((size_t)cig << 4)) : 0);
                uint32_t dst = pairbase + (uint32_t)(j * SLAB_STRIDE)
                             + (uint32_t)(px * 128 + ((cig ^ (px & 7)) << 4));
                cp16(dst, src, ok ? 16 : 0);
            }
        } else {
            // timeout fallback: convert this row directly from fp32 x (bit-identical)
#pragma unroll 1
            for (int c = lane; c < PXST * 8; c += 32) {
                int px  = c >> 3;
                int cig = c & 7;
                int ix  = x0 + px;
                uint32_t hw[4] = {0, 0, 0, 0};
                if (y < HH && ix < WW) {
                    const float* xp = x + (((size_t)(b * CIN + cig * 8)) * HH + y) * WW + ix;
#pragma unroll
                    for (int k = 0; k < 4; k++) {
                        float v0 = __ldg(xp + (size_t)(2 * k)     * HH * WW);
                        float v1 = __ldg(xp + (size_t)(2 * k + 1) * HH * WW);
                        __half2 h2 = __floats2half2_rn(v0, v1);
                        hw[k] = *(uint32_t*)&h2;
                    }
                }
                uint32_t dst = pairbase + (uint32_t)(j * SLAB_STRIDE)
                             + (uint32_t)(px * 128 + ((cig ^ (px & 7)) << 4));
                sts128(dst, hw[0], hw[1], hw[2], hw[3]);
            }
        }
        asm volatile("cp.async.commit_group;" ::: "memory");
    }

    // ---- weights ready? ----
    if (lane == 0) spin_ge(&g_wflag, 9, 100000);
    __syncwarp();

    // ---- accumulators, init = bias[co] ----
    float acc[4][4][4];
#pragma unroll
    for (int m = 0; m < 4; m++) {
        int r_co = warpM * 64 + m * 16 + (lane >> 2);
        float b0 = __ldg(&bias[r_co]);
        float b1 = __ldg(&bias[r_co + 8]);
#pragma unroll
        for (int f = 0; f < 4; f++) {
            acc[m][f][0] = b0; acc[m][f][1] = b0;
            acc[m][f][2] = b1; acc[m][f][3] = b1;
        }
    }

    const uint4* gw = g_Wfrag;
    const int pxl     = lane & 7;
    const int fhalf   = (lane >> 4) & 1;
    const int kb_lane = ((lane >> 3) & 1) * 16;
    const int awoff   = warpM * 4;
    const int barid   = pair + 1;

#pragma unroll
    for (int kh = 0; kh < 3; kh++) {
        if (kh == 0) {
            asm volatile("cp.async.wait_group 1;" ::: "memory");
        } else if (kh == 1) {
            if (warpM == 0) { asm volatile("cp.async.wait_group 0;" ::: "memory"); }
            else            { asm volatile("cp.async.wait_group 1;" ::: "memory"); }
        } else {
            asm volatile("cp.async.wait_group 0;" ::: "memory");
        }
        asm volatile("bar.sync %0, %1;" :: "r"(barid), "r"(64) : "memory");

        const uint32_t row0 = pairbase + (uint32_t)(kh * SLAB_STRIDE);
#pragma unroll
        for (int kw = 0; kw < 3; kw++) {
            const int tap = kh * 3 + kw;
#pragma unroll
            for (int ks = 0; ks < 4; ks++) {
                uint4 A[4];
                const int base = (tap * 4 + ks) * 8;
#pragma unroll
                for (int m = 0; m < 4; m++)
                    A[m] = __ldg(&gw[(base + awoff + m) * 32 + lane]);

                uint32_t B[8];
#pragma unroll
                for (int h = 0; h < 2; h++) {
                    uint32_t off = swz((uint32_t)((pxl + fhalf * 8 + kw) * 128 + kb_lane + ks * 32));
                    ldsm4(B[h*4+0], B[h*4+1], B[h*4+2], B[h*4+3],
                          row0 + (uint32_t)(h * SLAB_STRIDE) + off);
                }
#pragma unroll
                for (int m = 0; m < 4; m++) {
#pragma unroll
                    for (int f = 0; f < 4; f++)
                        mma16816(acc[m][f], A[m], B[f*2], B[f*2+1]);
                }
            }
        }
    }

    // ---- epilogue: min over co ----
    float* sMin = (float*)(smem_raw + (sb - smem_u32(smem_raw)) + OFF_MIN);

#pragma unroll
    for (int f = 0; f < 4; f++) {
        float v0 = __int_as_float(0x7f800000), v1 = v0;
#pragma unroll
        for (int m = 0; m < 4; m++) {
            v0 = fminf(v0, fminf(acc[m][f][0], acc[m][f][2]));
            v1 = fminf(v1, fminf(acc[m][f][1], acc[m][f][3]));
        }
#pragma unroll
        for (int off = 4; off < 32; off <<= 1) {
            v0 = fminf(v0, __shfl_xor_sync(0xffffffffu, v0, off));
            v1 = fminf(v1, __shfl_xor_sync(0xffffffffu, v1, off));
        }
        if ((lane >> 2) == 0) {
            int r_loc = 2 * pair + (f >> 1);
            int px    = (f & 1) * 8 + (lane & 3) * 2;
            int idx   = r_loc * TPX + px;
            sMin[warpM * 128 + idx]     = v0;
            sMin[warpM * 128 + idx + 1] = v1;
        }
    }
    __syncthreads();

    if (tid < 128) {
        int rr = tid >> 4, c = tid & 15;
        int orow = oy0 + rr, ocol = x0 + c;
        if (orow < OH && ocol < OW) {
            float m = fminf(sMin[tid], sMin[128 + tid]);
            out[((size_t)b * OH + orow) * OW + ocol] = tanhf(tanhf(m));
        }
    }

    // ---- replay-safe flag reset (last consumer zeroes) ----
    if (tid == 0) {
#pragma unroll 1
        for (int g = 0; g < 10; g++) {
            int y = oy0 + g;
            if (y >= HH) continue;
            int ty_lo = (y >= 9) ? ((y - 2) >> 3) : 0;
            int ty_hi = min(27, y >> 3);
            int tot   = NTX * (ty_hi - ty_lo + 1);
            int old = atomicAdd(&g_cons[b * HH + y], 1);
            if (old + 1 == tot) {
                atomicExch(&g_cons[b * HH + y], 0);
                atomicExch(&g_flag[b * HH + y], 0);
            }
        }
        int oldw = atomicAdd(&g_wcons, 1);
        if (oldw + 1 == NCONV) {
            atomicExch(&g_wcons, 0);
            atomicExch(&g_wflag, 0);
        }
    }
}

extern "C" void kernel_launch(void* const* d_in, const int* in_sizes, int n_in,
                              void* d_out, int out_size) {
    const float* x    = (const float*)d_in[0];
    const float* w    = (const float*)d_in[1];
    const float* bias = (const float*)d_in[2];
    float* out = (float*)d_out;

    static bool init = false;
    if (!init) {
        cudaFuncSetAttribute(fused_kernel, cudaFuncAttributeMaxDynamicSharedMemorySize, SMEM_BYTES);
        init = true;
    }
    fused_kernel<<<16 * BPB, 256, SMEM_BYTES>>>(x, w, bias, out);
}